// round 16
// baseline (speedup 1.0000x reference)
#include <cuda_runtime.h>
#include <cuda_fp16.h>
#include <cstdint>

// ============================================================================
// B=32, L=2048, E=512, Q=512.  cat=[query, emb] (K=1024)
//   h = tanh(cat @ W^T + b);  scores = h @ v_w;  w = softmax_L(scores)
//   applied = sum_l w * emb
// Output: applied (32*512) then weights (32*2048), fp32.
// R16 = R10 (best measured, 304.3us) with stsA moved into the MMA shadow
//       (between MMA groups of ks=0). asm volatile order == SASS order, so
//       this is a real scheduling change. Everything else identical to R10.
// ============================================================================

#define BATCH 32
#define SEQ   2048
#define EDIM  512
#define KDIM  1024
#define NTOK  (BATCH * SEQ)     // 65536
#define MT    128
#define NT    128
#define KC    32
#define NCH   (KDIM / KC)       // 32
#define NMT   (NTOK / MT)       // 512 m-tiles (16 per batch)
#define RSTR  80                // bytes per smem row (32 halves + 16B pad)
#define ABYTES (MT * RSTR)      // 10240
#define BBYTES (NT * RSTR)      // 10240

#define OFF_A   0
#define OFF_B   (2 * ABYTES)                  // 20480 (3 B stages)
#define OFF_BS  (OFF_B + 3 * BBYTES)          // 51200 : b_attn slice (128 f32)
#define OFF_VS  (OFF_BS + 512)
#define OFF_SC  (OFF_VS + 512)                // score partials 4*128 f32
#define SMEM_SZ (OFF_SC + 2048)               // 54272 (dynamic)

// ---- device scratch ----
__device__ __half g_wf16[EDIM * KDIM];        // W in f16, [e][k]
__device__ float  g_spart[4 * NTOK];          // per-n-tile partial scores
__device__ float  g_escores[NTOK];            // exp(score), unnormalized
__device__ float  g_zpart[NMT];               // per-m-tile sum of exp
__device__ float2 g_papply2[NMT * 256];       // per-m-tile partial applied
__device__ unsigned int g_cnt_mt[NMT];        // zero-init; reset after use

static __device__ __forceinline__ uint32_t smem_u32(const void* p) {
    uint32_t a;
    asm("{ .reg .u64 t; cvta.to.shared.u64 t, %1; cvt.u32.u64 %0, t; }"
        : "=r"(a) : "l"(p));
    return a;
}

static __device__ __forceinline__ uint32_t pack2(float x, float y) {
    __half2 h = __floats2half2_rn(x, y);
    return *reinterpret_cast<uint32_t*>(&h);
}

static __device__ __forceinline__ void sts128(uint32_t addr, uint32_t a, uint32_t b,
                                              uint32_t c, uint32_t d) {
    asm volatile("st.shared.v4.b32 [%0], {%1,%2,%3,%4};"
                 :: "r"(addr), "r"(a), "r"(b), "r"(c), "r"(d) : "memory");
}

static __device__ __forceinline__ void ldsm4(uint32_t* r, uint32_t addr) {
    asm volatile("ldmatrix.sync.aligned.m8n8.x4.shared.b16 {%0,%1,%2,%3}, [%4];"
                 : "=r"(r[0]), "=r"(r[1]), "=r"(r[2]), "=r"(r[3]) : "r"(addr));
}

static __device__ __forceinline__ void cpasync16(uint32_t dst, const void* src) {
    asm volatile("cp.async.cg.shared.global [%0], [%1], 16;" :: "r"(dst), "l"(src));
}

static __device__ __forceinline__ void mma16816(float* c, const uint32_t* a,
                                                uint32_t b0, uint32_t b1) {
    asm volatile(
        "mma.sync.aligned.m16n8k16.row.col.f32.f16.f16.f32 "
        "{%0,%1,%2,%3}, {%4,%5,%6,%7}, {%8,%9}, {%0,%1,%2,%3};"
        : "+f"(c[0]), "+f"(c[1]), "+f"(c[2]), "+f"(c[3])
        : "r"(a[0]), "r"(a[1]), "r"(a[2]), "r"(a[3]), "r"(b0), "r"(b1));
}

static __device__ __forceinline__ float fast_tanh(float x) {
    float t = __expf(2.0f * x);
    return 1.0f - __fdividef(2.0f, t + 1.0f);
}

// ============================================================================
// Kernel 0: W fp32 [512][1024] -> f16  (4 float4 per thread for ILP)
// ============================================================================
__global__ void convert_w_kernel(const float* __restrict__ W) {
    int i = blockIdx.x * blockDim.x + threadIdx.x;   // 32768 threads
#pragma unroll
    for (int j = 0; j < 4; j++) {
        int idx = i + j * 32768;                     // 131072 float4 total
        float4 v = reinterpret_cast<const float4*>(W)[idx];
        reinterpret_cast<__half2*>(g_wf16)[2 * idx]     = __floats2half2_rn(v.x, v.y);
        reinterpret_cast<__half2*>(g_wf16)[2 * idx + 1] = __floats2half2_rn(v.z, v.w);
    }
}

// ============================================================================
// Kernel 1: GEMM (R10 golden) + fused scores + per-m-tile exp/Z/partial-apply.
//           stsA interleaved into the ks=0 MMA shadow.
// ============================================================================
__global__ void __launch_bounds__(256, 2) gemm_kernel(
    const float* __restrict__ emb, const float* __restrict__ query,
    const float* __restrict__ b_attn, const float* __restrict__ v_w) {
    extern __shared__ __align__(16) char smem[];
    __shared__ unsigned int is_last;
    __shared__ float zred[4];
    const uint32_t sb = smem_u32(smem);
    const int tid = threadIdx.x, lane = tid & 31, wid = tid >> 5;
    const int nt = blockIdx.x, mt = blockIdx.y;
    const int m_base = mt * MT;
    const int wm = wid >> 2, wn = wid & 3;   // 2 x 4

    if (tid < NT) {
        reinterpret_cast<float*>(smem + OFF_BS)[tid] = b_attn[nt * NT + tid];
        reinterpret_cast<float*>(smem + OFF_VS)[tid] = v_w[nt * NT + tid];
    }

    float acc[4][4][4];
#pragma unroll
    for (int i = 0; i < 4; i++)
#pragma unroll
        for (int j = 0; j < 4; j++)
#pragma unroll
            for (int k = 0; k < 4; k++) acc[i][j][k] = 0.f;

    // ldmatrix lane offsets
    const uint32_t aOffLane = (uint32_t)((wm * 64 + (lane & 15)) * RSTR + (lane >> 4) * 16);
    const int g = lane >> 3, ls = lane & 7;
    const uint32_t bOffLane = (uint32_t)((wn * 32 + ((g >> 1) & 1) * 8 + ls) * RSTR + (g & 1) * 16);

    // A loader: 128 rows x 32 f32; row = tid>>1, half = tid&1 (16 f32)
    const int ar = tid >> 1, ach = tid & 1;
    // B loader: 128 rows x 64B; row = tid>>1, part = tid&1 (32B)
    const int br = tid >> 1, bp = tid & 1;
    const __half* wrow = g_wf16 + (size_t)(nt * NT + br) * KDIM + bp * 16;

    float4 f0, f1, f2, f3;
    auto ldgA = [&](int c) {
        const float* src = ((c < 16) ? query : emb) +
                           (size_t)(m_base + ar) * 512 + (c & 15) * KC + ach * 16;
        const float4* p = reinterpret_cast<const float4*>(src);
        f0 = p[0]; f1 = p[1]; f2 = p[2]; f3 = p[3];
    };
    auto stsA = [&](int buf) {
        uint32_t d = sb + OFF_A + buf * ABYTES + ar * RSTR + ach * 32;
        sts128(d, pack2(f0.x, f0.y), pack2(f0.z, f0.w), pack2(f1.x, f1.y), pack2(f1.z, f1.w));
        sts128(d + 16, pack2(f2.x, f2.y), pack2(f2.z, f2.w), pack2(f3.x, f3.y), pack2(f3.z, f3.w));
    };
    auto cpB = [&](int c, int buf) {
        const __half* src = wrow + c * KC;
        uint32_t d = sb + OFF_B + buf * BBYTES + br * RSTR + bp * 32;
        cpasync16(d, src);
        cpasync16(d + 16, src + 8);
        asm volatile("cp.async.commit_group;" ::: "memory");
    };

    // prologue: B chunks 0 and 1 in flight, A chunk 0 staged
    ldgA(0);
    cpB(0, 0);
    cpB(1, 1);
    stsA(0);

    for (int c = 0; c < NCH; c++) {
        const int abuf = c & 1;
        const int bbuf = c % 3;
        if (c + 1 < NCH) ldgA(c + 1);   // issue LDG before the stall point
        if (c < NCH - 1) {
            asm volatile("cp.async.wait_group 1;" ::: "memory");
        } else {
            asm volatile("cp.async.wait_group 0;" ::: "memory");
        }
        __syncthreads();

        if (c + 2 < NCH) cpB(c + 2, (c + 2) % 3);

        const uint32_t aBase = sb + OFF_A + abuf * ABYTES + aOffLane;
        const uint32_t bBase = sb + OFF_B + bbuf * BBYTES + bOffLane;

        // ---- ks = 0: load frags, run MMAs with stsA in the shadow ----
        {
            uint32_t a[4][4], bb[2][4];
#pragma unroll
            for (int mi = 0; mi < 4; mi++)
                ldsm4(a[mi], aBase + mi * 16 * RSTR);
#pragma unroll
            for (int np = 0; np < 2; np++)
                ldsm4(bb[np], bBase + np * 16 * RSTR);
#pragma unroll
            for (int mi = 0; mi < 2; mi++)
#pragma unroll
                for (int ni = 0; ni < 4; ni++)
                    mma16816(acc[mi][ni], a[mi],
                             bb[ni >> 1][(ni & 1) * 2], bb[ni >> 1][(ni & 1) * 2 + 1]);

            if (c + 1 < NCH) stsA(abuf ^ 1);   // STS under tensor-pipe cover

#pragma unroll
            for (int mi = 2; mi < 4; mi++)
#pragma unroll
                for (int ni = 0; ni < 4; ni++)
                    mma16816(acc[mi][ni], a[mi],
                             bb[ni >> 1][(ni & 1) * 2], bb[ni >> 1][(ni & 1) * 2 + 1]);
        }
        // ---- ks = 1 ----
        {
            uint32_t a[4][4], bb[2][4];
#pragma unroll
            for (int mi = 0; mi < 4; mi++)
                ldsm4(a[mi], aBase + mi * 16 * RSTR + 32);
#pragma unroll
            for (int np = 0; np < 2; np++)
                ldsm4(bb[np], bBase + np * 16 * RSTR + 32);
#pragma unroll
            for (int mi = 0; mi < 4; mi++)
#pragma unroll
                for (int ni = 0; ni < 4; ni++)
                    mma16816(acc[mi][ni], a[mi],
                             bb[ni >> 1][(ni & 1) * 2], bb[ni >> 1][(ni & 1) * 2 + 1]);
        }
    }

    // ---- fused epilogue: partial score = sum_col tanh(acc + b) * v_w ----
    const float* bs = reinterpret_cast<const float*>(smem + OFF_BS);
    const float* vs = reinterpret_cast<const float*>(smem + OFF_VS);
    float* scs = reinterpret_cast<float*>(smem + OFF_SC);

    float ps[4][2];
#pragma unroll
    for (int mi = 0; mi < 4; mi++) { ps[mi][0] = 0.f; ps[mi][1] = 0.f; }

#pragma unroll
    for (int mi = 0; mi < 4; mi++)
#pragma unroll
        for (int ni = 0; ni < 4; ni++)
#pragma unroll
            for (int r = 0; r < 4; r++) {
                int col = wn * 32 + ni * 8 + (lane & 3) * 2 + (r & 1);
                float t = fast_tanh(acc[mi][ni][r] + bs[col]);
                ps[mi][r >> 1] += t * vs[col];
            }

#pragma unroll
    for (int mi = 0; mi < 4; mi++)
#pragma unroll
        for (int h = 0; h < 2; h++) {
            float v = ps[mi][h];
            v += __shfl_xor_sync(0xffffffffu, v, 1);
            v += __shfl_xor_sync(0xffffffffu, v, 2);
            if ((lane & 3) == 0)
                scs[wn * 128 + wm * 64 + mi * 16 + h * 8 + (lane >> 2)] = v;
        }
    __syncthreads();

    if (tid < MT) {
        float s = scs[tid] + scs[128 + tid] + scs[256 + tid] + scs[384 + tid];
        g_spart[nt * NTOK + m_base + tid] = s;
    }

    // ---- last-of-4 CTA for this m-tile: exp, Z, partial apply ----
    __threadfence();
    __syncthreads();
    if (tid == 0)
        is_last = (atomicInc(&g_cnt_mt[mt], 0xFFFFFFFFu) == 3u);
    __syncthreads();
    if (!is_last) return;

    float* ws = reinterpret_cast<float*>(smem + OFF_SC);   // reuse: 128 exps
    if (tid < MT) {
        float s = g_spart[m_base + tid] + g_spart[NTOK + m_base + tid] +
                  g_spart[2 * NTOK + m_base + tid] + g_spart[3 * NTOK + m_base + tid];
        float e = __expf(s);
        g_escores[m_base + tid] = e;
        ws[tid] = e;
        float z = e;
#pragma unroll
        for (int off = 16; off > 0; off >>= 1)
            z += __shfl_xor_sync(0xffffffffu, z, off);
        if (lane == 0) zred[wid] = z;
    }
    __syncthreads();
    if (tid == 0) {
        g_zpart[mt] = zred[0] + zred[1] + zred[2] + zred[3];
        g_cnt_mt[mt] = 0u;               // reset for next graph replay
    }

    // partial apply: 256 threads, each a float2 column pair over 128 rows
    const float2* ep = reinterpret_cast<const float2*>(emb) + (size_t)m_base * 256 + tid;
    float2 a = {0.f, 0.f};
#pragma unroll 8
    for (int l = 0; l < 128; l++) {
        float wv = ws[l];
        float2 v = ep[(size_t)l * 256];
        a.x += wv * v.x;
        a.y += wv * v.y;
    }
    g_papply2[mt * 256 + tid] = a;
}

// ============================================================================
// Kernel 2: finalize — per batch: Z, applied = sum(partials)/Z, weights = e/Z
// ============================================================================
__global__ void finalize_kernel(float* __restrict__ applied_out,
                                float* __restrict__ weights_out) {
    __shared__ float zinv;
    const int b = blockIdx.x;        // 32
    const int tid = threadIdx.x;     // 512
    if (tid == 0) {
        float z = 0.f;
#pragma unroll
        for (int j = 0; j < 16; j++) z += g_zpart[b * 16 + j];
        zinv = 1.0f / z;
    }
    __syncthreads();
    const float inv = zinv;

    // applied: column tid
    const float* pp = reinterpret_cast<const float*>(g_papply2);
    float s = 0.f;
#pragma unroll
    for (int j = 0; j < 16; j++) s += pp[(b * 16 + j) * 512 + tid];
    applied_out[b * EDIM + tid] = s * inv;

    // weights: 2048 tokens
#pragma unroll
    for (int i = 0; i < 4; i++) {
        int t = i * 512 + tid;
        weights_out[b * SEQ + t] = g_escores[b * SEQ + t] * inv;
    }
}

// ============================================================================
// kernel_launch
// ============================================================================
extern "C" void kernel_launch(void* const* d_in, const int* in_sizes, int n_in,
                              void* d_out, int out_size) {
    const float* emb    = (const float*)d_in[0];
    const float* query  = (const float*)d_in[1];
    const float* W_attn = (const float*)d_in[2];
    const float* b_attn = (const float*)d_in[3];
    const float* v_w    = (const float*)d_in[4];
    float* out = (float*)d_out;
    float* applied_out = out;                 // 32*512
    float* weights_out = out + BATCH * EDIM;  // 32*2048

    cudaFuncSetAttribute(gemm_kernel,
                         cudaFuncAttributeMaxDynamicSharedMemorySize, SMEM_SZ);

    convert_w_kernel<<<128, 256>>>(W_attn);
    gemm_kernel<<<dim3(4, NMT), 256, SMEM_SZ>>>(emb, query, b_attn, v_w);
    finalize_kernel<<<BATCH, 512>>>(applied_out, weights_out);
}

// round 17
// speedup vs baseline: 1.3293x; 1.3293x over previous
#include <cuda_runtime.h>
#include <cuda_fp16.h>
#include <cstdint>

// ============================================================================
// B=32, L=2048, E=512, Q=512.  cat=[query, emb] (K=1024)
//   h = tanh(cat @ W^T + b);  scores = h @ v_w;  w = softmax_L(scores)
//   applied = sum_l w * emb
// Output: applied (32*512) then weights (32*2048), fp32.
// R17 = R10 (best, 304.3us) with COALESCED loaders:
//   A: 8 threads/row -> each LDG.128 warp-instr touches 4 lines (was 16)
//   B: 4 threads/row -> each cp.async warp-instr touches 8 lines (was 16)
// Same bytes, same smem layout, same loop structure. Pure L1-wavefront cut.
// ============================================================================

#define BATCH 32
#define SEQ   2048
#define EDIM  512
#define KDIM  1024
#define NTOK  (BATCH * SEQ)     // 65536
#define MT    128
#define NT    128
#define KC    32
#define NCH   (KDIM / KC)       // 32
#define NMT   (NTOK / MT)       // 512 m-tiles (16 per batch)
#define RSTR  80                // bytes per smem row (32 halves + 16B pad)
#define ABYTES (MT * RSTR)      // 10240
#define BBYTES (NT * RSTR)      // 10240

#define OFF_A   0
#define OFF_B   (2 * ABYTES)                  // 20480 (3 B stages)
#define OFF_BS  (OFF_B + 3 * BBYTES)          // 51200 : b_attn slice (128 f32)
#define OFF_VS  (OFF_BS + 512)
#define OFF_SC  (OFF_VS + 512)                // score partials 4*128 f32
#define SMEM_SZ (OFF_SC + 2048)               // 54272 (dynamic)

// ---- device scratch ----
__device__ __half g_wf16[EDIM * KDIM];        // W in f16, [e][k]
__device__ float  g_spart[4 * NTOK];          // per-n-tile partial scores
__device__ float  g_escores[NTOK];            // exp(score), unnormalized
__device__ float  g_zpart[NMT];               // per-m-tile sum of exp
__device__ float2 g_papply2[NMT * 256];       // per-m-tile partial applied
__device__ unsigned int g_cnt_mt[NMT];        // zero-init; reset after use

static __device__ __forceinline__ uint32_t smem_u32(const void* p) {
    uint32_t a;
    asm("{ .reg .u64 t; cvta.to.shared.u64 t, %1; cvt.u32.u64 %0, t; }"
        : "=r"(a) : "l"(p));
    return a;
}

static __device__ __forceinline__ uint32_t pack2(float x, float y) {
    __half2 h = __floats2half2_rn(x, y);
    return *reinterpret_cast<uint32_t*>(&h);
}

static __device__ __forceinline__ void sts64(uint32_t addr, uint32_t a, uint32_t b) {
    asm volatile("st.shared.v2.b32 [%0], {%1,%2};"
                 :: "r"(addr), "r"(a), "r"(b) : "memory");
}

static __device__ __forceinline__ void ldsm4(uint32_t* r, uint32_t addr) {
    asm volatile("ldmatrix.sync.aligned.m8n8.x4.shared.b16 {%0,%1,%2,%3}, [%4];"
                 : "=r"(r[0]), "=r"(r[1]), "=r"(r[2]), "=r"(r[3]) : "r"(addr));
}

static __device__ __forceinline__ void cpasync16(uint32_t dst, const void* src) {
    asm volatile("cp.async.cg.shared.global [%0], [%1], 16;" :: "r"(dst), "l"(src));
}

static __device__ __forceinline__ void mma16816(float* c, const uint32_t* a,
                                                uint32_t b0, uint32_t b1) {
    asm volatile(
        "mma.sync.aligned.m16n8k16.row.col.f32.f16.f16.f32 "
        "{%0,%1,%2,%3}, {%4,%5,%6,%7}, {%8,%9}, {%0,%1,%2,%3};"
        : "+f"(c[0]), "+f"(c[1]), "+f"(c[2]), "+f"(c[3])
        : "r"(a[0]), "r"(a[1]), "r"(a[2]), "r"(a[3]), "r"(b0), "r"(b1));
}

static __device__ __forceinline__ float fast_tanh(float x) {
    float t = __expf(2.0f * x);
    return 1.0f - __fdividef(2.0f, t + 1.0f);
}

// ============================================================================
// Kernel 0: W fp32 [512][1024] -> f16  (4 float4 per thread for ILP)
// ============================================================================
__global__ void convert_w_kernel(const float* __restrict__ W) {
    int i = blockIdx.x * blockDim.x + threadIdx.x;   // 32768 threads
#pragma unroll
    for (int j = 0; j < 4; j++) {
        int idx = i + j * 32768;                     // 131072 float4 total
        float4 v = reinterpret_cast<const float4*>(W)[idx];
        reinterpret_cast<__half2*>(g_wf16)[2 * idx]     = __floats2half2_rn(v.x, v.y);
        reinterpret_cast<__half2*>(g_wf16)[2 * idx + 1] = __floats2half2_rn(v.z, v.w);
    }
}

// ============================================================================
// Kernel 1: GEMM (R10 golden loop) + coalesced loaders + fused scores
//           + per-m-tile exp/Z/partial-apply (last-of-4 CTA).
// ============================================================================
__global__ void __launch_bounds__(256, 2) gemm_kernel(
    const float* __restrict__ emb, const float* __restrict__ query,
    const float* __restrict__ b_attn, const float* __restrict__ v_w) {
    extern __shared__ __align__(16) char smem[];
    __shared__ unsigned int is_last;
    __shared__ float zred[4];
    const uint32_t sb = smem_u32(smem);
    const int tid = threadIdx.x, lane = tid & 31, wid = tid >> 5;
    const int nt = blockIdx.x, mt = blockIdx.y;
    const int m_base = mt * MT;
    const int wm = wid >> 2, wn = wid & 3;   // 2 x 4

    if (tid < NT) {
        reinterpret_cast<float*>(smem + OFF_BS)[tid] = b_attn[nt * NT + tid];
        reinterpret_cast<float*>(smem + OFF_VS)[tid] = v_w[nt * NT + tid];
    }

    float acc[4][4][4];
#pragma unroll
    for (int i = 0; i < 4; i++)
#pragma unroll
        for (int j = 0; j < 4; j++)
#pragma unroll
            for (int k = 0; k < 4; k++) acc[i][j][k] = 0.f;

    // ldmatrix lane offsets
    const uint32_t aOffLane = (uint32_t)((wm * 64 + (lane & 15)) * RSTR + (lane >> 4) * 16);
    const int g = lane >> 3, ls = lane & 7;
    const uint32_t bOffLane = (uint32_t)((wn * 32 + ((g >> 1) & 1) * 8 + ls) * RSTR + (g & 1) * 16);

    // A loader: 8 threads/row (16B each), 4 row-groups of 32 rows
    const int ar = tid >> 3, aseg = tid & 7;
    // B loader: 4 threads/row (16B each), 2 row-groups of 64 rows
    const int br = tid >> 2, bp = tid & 3;
    const __half* wrow = g_wf16 + (size_t)(nt * NT + br) * KDIM + bp * 8;

    float4 fA[4];
    auto ldgA = [&](int c) {
        const float* src = ((c < 16) ? query : emb) +
                           (size_t)(m_base + ar) * 512 + (c & 15) * KC + aseg * 4;
#pragma unroll
        for (int i = 0; i < 4; i++)
            fA[i] = *reinterpret_cast<const float4*>(src + (size_t)i * 32 * 512);
    };
    auto stsA = [&](int buf) {
        uint32_t d = sb + OFF_A + buf * ABYTES + ar * RSTR + aseg * 8;
#pragma unroll
        for (int i = 0; i < 4; i++)
            sts64(d + i * 32 * RSTR, pack2(fA[i].x, fA[i].y), pack2(fA[i].z, fA[i].w));
    };
    auto cpB = [&](int c, int buf) {
        const __half* src = wrow + c * KC;
        uint32_t d = sb + OFF_B + buf * BBYTES + br * RSTR + bp * 16;
        cpasync16(d, src);
        cpasync16(d + 64 * RSTR, src + (size_t)64 * KDIM);
        asm volatile("cp.async.commit_group;" ::: "memory");
    };

    // prologue: B chunks 0 and 1 in flight, A chunk 0 staged
    ldgA(0);
    cpB(0, 0);
    cpB(1, 1);
    stsA(0);

    for (int c = 0; c < NCH; c++) {
        const int abuf = c & 1;
        const int bbuf = c % 3;
        if (c + 1 < NCH) ldgA(c + 1);   // issue LDG before the stall point
        if (c < NCH - 1) {
            asm volatile("cp.async.wait_group 1;" ::: "memory");
        } else {
            asm volatile("cp.async.wait_group 0;" ::: "memory");
        }
        __syncthreads();

        if (c + 2 < NCH) cpB(c + 2, (c + 2) % 3);

        const uint32_t aBase = sb + OFF_A + abuf * ABYTES + aOffLane;
        const uint32_t bBase = sb + OFF_B + bbuf * BBYTES + bOffLane;
#pragma unroll
        for (int ks = 0; ks < 2; ks++) {
            uint32_t a[4][4], bb[2][4];
#pragma unroll
            for (int mi = 0; mi < 4; mi++)
                ldsm4(a[mi], aBase + mi * 16 * RSTR + ks * 32);
#pragma unroll
            for (int np = 0; np < 2; np++)
                ldsm4(bb[np], bBase + np * 16 * RSTR + ks * 32);
#pragma unroll
            for (int mi = 0; mi < 4; mi++)
#pragma unroll
                for (int ni = 0; ni < 4; ni++)
                    mma16816(acc[mi][ni], a[mi],
                             bb[ni >> 1][(ni & 1) * 2], bb[ni >> 1][(ni & 1) * 2 + 1]);
        }

        if (c + 1 < NCH) stsA(abuf ^ 1);
    }

    // ---- fused epilogue: partial score = sum_col tanh(acc + b) * v_w ----
    const float* bs = reinterpret_cast<const float*>(smem + OFF_BS);
    const float* vs = reinterpret_cast<const float*>(smem + OFF_VS);
    float* scs = reinterpret_cast<float*>(smem + OFF_SC);

    float ps[4][2];
#pragma unroll
    for (int mi = 0; mi < 4; mi++) { ps[mi][0] = 0.f; ps[mi][1] = 0.f; }

#pragma unroll
    for (int mi = 0; mi < 4; mi++)
#pragma unroll
        for (int ni = 0; ni < 4; ni++)
#pragma unroll
            for (int r = 0; r < 4; r++) {
                int col = wn * 32 + ni * 8 + (lane & 3) * 2 + (r & 1);
                float t = fast_tanh(acc[mi][ni][r] + bs[col]);
                ps[mi][r >> 1] += t * vs[col];
            }

#pragma unroll
    for (int mi = 0; mi < 4; mi++)
#pragma unroll
        for (int h = 0; h < 2; h++) {
            float v = ps[mi][h];
            v += __shfl_xor_sync(0xffffffffu, v, 1);
            v += __shfl_xor_sync(0xffffffffu, v, 2);
            if ((lane & 3) == 0)
                scs[wn * 128 + wm * 64 + mi * 16 + h * 8 + (lane >> 2)] = v;
        }
    __syncthreads();

    if (tid < MT) {
        float s = scs[tid] + scs[128 + tid] + scs[256 + tid] + scs[384 + tid];
        g_spart[nt * NTOK + m_base + tid] = s;
    }

    // ---- last-of-4 CTA for this m-tile: exp, Z, partial apply ----
    __threadfence();
    __syncthreads();
    if (tid == 0)
        is_last = (atomicInc(&g_cnt_mt[mt], 0xFFFFFFFFu) == 3u);
    __syncthreads();
    if (!is_last) return;

    float* ws = reinterpret_cast<float*>(smem + OFF_SC);   // reuse: 128 exps
    if (tid < MT) {
        float s = g_spart[m_base + tid] + g_spart[NTOK + m_base + tid] +
                  g_spart[2 * NTOK + m_base + tid] + g_spart[3 * NTOK + m_base + tid];
        float e = __expf(s);
        g_escores[m_base + tid] = e;
        ws[tid] = e;
        float z = e;
#pragma unroll
        for (int off = 16; off > 0; off >>= 1)
            z += __shfl_xor_sync(0xffffffffu, z, off);
        if (lane == 0) zred[wid] = z;
    }
    __syncthreads();
    if (tid == 0) {
        g_zpart[mt] = zred[0] + zred[1] + zred[2] + zred[3];
        g_cnt_mt[mt] = 0u;               // reset for next graph replay
    }

    // partial apply: 256 threads, each a float2 column pair over 128 rows
    const float2* ep = reinterpret_cast<const float2*>(emb) + (size_t)m_base * 256 + tid;
    float2 a = {0.f, 0.f};
#pragma unroll 8
    for (int l = 0; l < 128; l++) {
        float wv = ws[l];
        float2 v = ep[(size_t)l * 256];
        a.x += wv * v.x;
        a.y += wv * v.y;
    }
    g_papply2[mt * 256 + tid] = a;
}

// ============================================================================
// Kernel 2: finalize — per batch: Z, applied = sum(partials)/Z, weights = e/Z
// ============================================================================
__global__ void finalize_kernel(float* __restrict__ applied_out,
                                float* __restrict__ weights_out) {
    __shared__ float zinv;
    const int b = blockIdx.x;        // 32
    const int tid = threadIdx.x;     // 512
    if (tid == 0) {
        float z = 0.f;
#pragma unroll
        for (int j = 0; j < 16; j++) z += g_zpart[b * 16 + j];
        zinv = 1.0f / z;
    }
    __syncthreads();
    const float inv = zinv;

    // applied: column tid
    const float* pp = reinterpret_cast<const float*>(g_papply2);
    float s = 0.f;
#pragma unroll
    for (int j = 0; j < 16; j++) s += pp[(b * 16 + j) * 512 + tid];
    applied_out[b * EDIM + tid] = s * inv;

    // weights: 2048 tokens
#pragma unroll
    for (int i = 0; i < 4; i++) {
        int t = i * 512 + tid;
        weights_out[b * SEQ + t] = g_escores[b * SEQ + t] * inv;
    }
}

// ============================================================================
// kernel_launch
// ============================================================================
extern "C" void kernel_launch(void* const* d_in, const int* in_sizes, int n_in,
                              void* d_out, int out_size) {
    const float* emb    = (const float*)d_in[0];
    const float* query  = (const float*)d_in[1];
    const float* W_attn = (const float*)d_in[2];
    const float* b_attn = (const float*)d_in[3];
    const float* v_w    = (const float*)d_in[4];
    float* out = (float*)d_out;
    float* applied_out = out;                 // 32*512
    float* weights_out = out + BATCH * EDIM;  // 32*2048

    cudaFuncSetAttribute(gemm_kernel,
                         cudaFuncAttributeMaxDynamicSharedMemorySize, SMEM_SZ);

    convert_w_kernel<<<128, 256>>>(W_attn);
    gemm_kernel<<<dim3(4, NMT), 256, SMEM_SZ>>>(emb, query, b_attn, v_w);
    finalize_kernel<<<BATCH, 512>>>(applied_out, weights_out);
}